// round 16
// baseline (speedup 1.0000x reference)
#include <cuda_runtime.h>
#include <cuda_fp16.h>

#define D     128
#define NMAX  50000
#define EMAX  600000
#define GMAX  64

// ---------------- device scratch ---------------------------------------------
// X planes interleaved (fp16): X4[r*32 + j] = {hi(2j), hi(2j+1), lo(2j), lo(2j+1)}
__device__ uint4 g_x4[NMAX * 32];
// W^T single fp16 plane per layer: W2[l*4096 + n*32 + j] = {w(2j), w(2j+1)}
__device__ uint2 g_w2[3 * 4096];
__device__ __half g_zh[NMAX * D];                // Z = (X @ W) * ns  (fp16)
__device__ float g_ns[NMAX];
__device__ float g_nd[NMAX];
__device__ float g_gsum[GMAX * D];
__device__ int   g_row_start[NMAX + 1];
__device__ int   g_cursor[NMAX];
__device__ int   g_col[EMAX];

// ---------------- helpers ----------------------------------------------------
__device__ __forceinline__ void redv4(float* p, float4 v) {
    asm volatile(
        "{\n\t"
        ".reg .u64 gp;\n\t"
        "cvta.to.global.u64 gp, %0;\n\t"
        "red.global.add.v4.f32 [gp], {%1, %2, %3, %4};\n\t"
        "}"
        :: "l"(p), "f"(v.x), "f"(v.y), "f"(v.z), "f"(v.w)
        : "memory");
}

// m16n8k16 fp16 MMA, fp32 accum (layout per CUTLASS SM80_16x8x16 TN)
__device__ __forceinline__ void mma_fp16(float c[4], const unsigned a[4],
                                         unsigned b0, unsigned b1) {
    asm("mma.sync.aligned.m16n8k16.row.col.f32.f16.f16.f32 "
        "{%0,%1,%2,%3}, {%4,%5,%6,%7}, {%8,%9}, {%0,%1,%2,%3};"
        : "+f"(c[0]), "+f"(c[1]), "+f"(c[2]), "+f"(c[3])
        : "r"(a[0]), "r"(a[1]), "r"(a[2]), "r"(a[3]), "r"(b0), "r"(b1));
}

// word index u (0..63) for fp16-pair k2 (0..63): u = ks*8 + tig*2 + kh
__device__ __forceinline__ int chunk_u(int k2) {
    return ((k2 >> 3) << 3) + ((k2 & 3) << 1) + ((k2 >> 2) & 1);
}

// pack two f32 -> fp16x2
__device__ __forceinline__ unsigned h2pack(float e0, float e1) {
    __half2 h = __floats2half2_rn(e0, e1);
    return *(unsigned*)&h;
}

// split one f32 pair into fp16 hi/lo planes (hi + lo represents x to ~2^-23)
__device__ __forceinline__ void split2h(float x0, float x1, unsigned& hp, unsigned& lp) {
    __half2 h = __floats2half2_rn(x0, x1);
    float2 r = __half22float2(h);
    __half2 l = __floats2half2_rn(x0 - r.x, x1 - r.y);
    hp = *(unsigned*)&h;
    lp = *(unsigned*)&l;
}

// ---------------- #1: degrees + X-plane convert + W-plane convert ------------
__global__ __launch_bounds__(256)
void k_prep(const int* __restrict__ src, const int* __restrict__ dst,
            float* __restrict__ ns, float* __restrict__ nd, int E,
            const float* __restrict__ h, uint4* __restrict__ X4, int N,
            const float* __restrict__ W1, const float* __restrict__ W2,
            const float* __restrict__ W3, uint2* __restrict__ Wp) {
    int g = blockIdx.x * blockDim.x + threadIdx.x;
    int stride = gridDim.x * blockDim.x;

    for (int e = g; e < E; e += stride) {
        atomicAdd(&ns[src[e]], 1.0f);
        atomicAdd(&nd[dst[e]], 1.0f);
    }

    // X: one uint4 per (r, j); words 2j (k2a) and 2j+1 (k2b), fp16 hi/lo
    int nx = N * 32;
    for (int i = g; i < nx; i += stride) {
        int r = i >> 5, j = i & 31;
        int ks = j >> 2, tig = j & 3;
        int k2a = ks * 8 + tig;        // kh = 0
        int k2b = ks * 8 + 4 + tig;    // kh = 1
        float2 va = *(const float2*)(h + (size_t)r * 128 + k2a * 2);
        float2 vb = *(const float2*)(h + (size_t)r * 128 + k2b * 2);
        unsigned h0, l0, h1, l1;
        split2h(va.x, va.y, h0, l0);
        split2h(vb.x, vb.y, h1, l1);
        X4[i] = make_uint4(h0, h1, l0, l1);
    }

    // W^T: one uint2 per (l, n, j); single fp16 plane; source W[k][n]
    for (int i = g; i < 3 * 4096; i += stride) {
        int l = i >> 12, j2 = i & 4095;
        int n = j2 >> 5, j = j2 & 31;
        int ks = j >> 2, tig = j & 3;
        int k2a = ks * 8 + tig;
        int k2b = ks * 8 + 4 + tig;
        const float* W = (l == 0) ? W1 : (l == 1) ? W2 : W3;
        unsigned w0 = h2pack(W[(2 * k2a) * 128 + n], W[(2 * k2a + 1) * 128 + n]);
        unsigned w1 = h2pack(W[(2 * k2b) * 128 + n], W[(2 * k2b + 1) * 128 + n]);
        Wp[i] = make_uint2(w0, w1);
    }
}

// ---------------- #2: row_start scan + cursor + norms ------------------------
__global__ __launch_bounds__(256)
void k_rowstart_norm(float* __restrict__ ns, float* __restrict__ nd,
                     int* __restrict__ row_start, int* __restrict__ cursor,
                     int N, int E) {
    __shared__ int s[256];
    int tid = threadIdx.x;
    int base0 = blockIdx.x * 256;

    int acc = 0;
    for (int i = tid; i < base0; i += 256) acc += (int)nd[i];
    s[tid] = acc;
    __syncthreads();
    for (int off = 128; off > 0; off >>= 1) {
        if (tid < off) s[tid] += s[tid + off];
        __syncthreads();
    }
    int base = s[0];
    __syncthreads();

    int i = base0 + tid;
    int deg = (i < N) ? (int)nd[i] : 0;
    s[tid] = deg;
    __syncthreads();
    for (int off = 1; off < 256; off <<= 1) {
        int t = (tid >= off) ? s[tid - off] : 0;
        __syncthreads();
        s[tid] += t;
        __syncthreads();
    }

    if (i < N) {
        int rs = base + s[tid] - deg;
        row_start[i] = rs;
        cursor[i] = rs;
        if (i == N - 1) row_start[N] = E;
        ns[i] = rsqrtf(fmaxf(ns[i], 1.0f));
        nd[i] = rsqrtf(fmaxf(nd[i], 1.0f));
    }
}

// ---------------- #3: scatter edges into CSR ---------------------------------
__global__ void k_fill(const int* __restrict__ src, const int* __restrict__ dst,
                       int* __restrict__ cursor, int* __restrict__ col, int E) {
    int e = blockIdx.x * blockDim.x + threadIdx.x;
    if (e < E) {
        int pos = atomicAdd(&cursor[dst[e]], 1);
        col[pos] = src[e];
    }
}

// ---------------- tensor-core GEMM: Z = (X @ W) * ns[:,None] -----------------
// 2-product fp16 split ((Xh + Xl) @ W_fp16), fp32 accum. EXACT R15 mainloop;
// only change: __launch_bounds__(256, 2) so ptxas fits 128 regs -> 2 blocks/SM
// (4 warps/SMSP doubles latency hiding; live set ~110 regs, should not spill).
__global__ __launch_bounds__(256, 2)
void k_gemm(const uint4* __restrict__ X4, const uint2* __restrict__ Wp,
            const float* __restrict__ ns, __half* __restrict__ Zh, int N) {
    int tid  = threadIdx.x;
    int lane = tid & 31;
    int wid  = tid >> 5;
    int gid  = lane >> 2;      // 0..7
    int tig  = lane & 3;       // 0..3

    int row0  = blockIdx.x * 128 + (wid & 1) * 64;
    int nbase = (wid >> 1) * 32;

    float c[4][4][4];
#pragma unroll
    for (int mt = 0; mt < 4; mt++)
#pragma unroll
        for (int nt = 0; nt < 4; nt++)
#pragma unroll
            for (int q = 0; q < 4; q++) c[mt][nt][q] = 0.f;

#pragma unroll
    for (int ks = 0; ks < 8; ks++) {
        unsigned ah[4][4], al[4][4];
#pragma unroll
        for (int mt = 0; mt < 4; mt++) {
            int r  = row0 + mt * 16 + gid;
            int r8 = r + 8;
            int rc  = (r  < N) ? r  : N - 1;
            int rc8 = (r8 < N) ? r8 : N - 1;
            uint4 v1 = __ldg(&X4[(size_t)rc  * 32 + ks * 4 + tig]); // a0,a2 planes
            uint4 v2 = __ldg(&X4[(size_t)rc8 * 32 + ks * 4 + tig]); // a1,a3 planes
            ah[mt][0] = v1.x; ah[mt][2] = v1.y;
            ah[mt][1] = v2.x; ah[mt][3] = v2.y;
            al[mt][0] = v1.z; al[mt][2] = v1.w;
            al[mt][1] = v2.z; al[mt][3] = v2.w;
        }
#pragma unroll
        for (int nt = 0; nt < 4; nt++) {
            int n = nbase + nt * 8 + gid;
            uint2 B = __ldg(&Wp[n * 32 + ks * 4 + tig]);  // {b0, b1} fp16 plane
#pragma unroll
            for (int mt = 0; mt < 4; mt++) {
                mma_fp16(c[mt][nt], ah[mt], B.x, B.y);
                mma_fp16(c[mt][nt], al[mt], B.x, B.y);
            }
        }
    }

#pragma unroll
    for (int mt = 0; mt < 4; mt++) {
        int r  = row0 + mt * 16 + gid;
        int r8 = r + 8;
        float s1 = (r  < N) ? __ldg(&ns[r])  : 0.f;
        float s2 = (r8 < N) ? __ldg(&ns[r8]) : 0.f;
#pragma unroll
        for (int nt = 0; nt < 4; nt++) {
            int colx = nbase + nt * 8 + tig * 2;
            if (r < N)
                *(__half2*)(Zh + (size_t)r * 128 + colx) =
                    __floats2half2_rn(c[mt][nt][0] * s1, c[mt][nt][1] * s1);
            if (r8 < N)
                *(__half2*)(Zh + (size_t)r8 * 128 + colx) =
                    __floats2half2_rn(c[mt][nt][2] * s2, c[mt][nt][3] * s2);
        }
    }
}

// ---------------- gather: y = relu(nd * segsum(Z[src]) + b) ------------------
// Warp per destination row; Z is fp16 (half the LTS bytes), fp32 accumulate.
// POOL=false: writes interleaved fp16 hi/lo planes for the next layer.
// POOL=true: per-graph smem merge + vector REDs into gsum.
template <bool POOL>
__global__ __launch_bounds__(256)
void k_gather(const __half* __restrict__ Zh,
              const int* __restrict__ row_start, const int* __restrict__ col,
              const float* __restrict__ nd, const float* __restrict__ b,
              uint4* __restrict__ X4,
              const int* __restrict__ gid_arr, float* __restrict__ gsum, int N) {
    int tid  = threadIdx.x;
    int lane = tid & 31;
    int wid  = tid >> 5;
    int row  = blockIdx.x * 8 + wid;

    const uint2* z2 = (const uint2*)Zh;   // 4 halves per lane (cols lane*4..+3)
    float4 a0 = make_float4(0.f, 0.f, 0.f, 0.f);
    float4 a1 = make_float4(0.f, 0.f, 0.f, 0.f);

    if (row < N) {
        int e0 = __ldg(&row_start[row]);
        int e1 = __ldg(&row_start[row + 1]);
        int e  = e0;
        for (; e + 3 < e1; e += 4) {
            int s0 = __ldg(&col[e]);
            int s1 = __ldg(&col[e + 1]);
            int s2 = __ldg(&col[e + 2]);
            int s3 = __ldg(&col[e + 3]);
            uint2 v0 = __ldg(&z2[(size_t)s0 * 32 + lane]);
            uint2 v1 = __ldg(&z2[(size_t)s1 * 32 + lane]);
            uint2 v2 = __ldg(&z2[(size_t)s2 * 32 + lane]);
            uint2 v3 = __ldg(&z2[(size_t)s3 * 32 + lane]);
            float2 f;
            f = __half22float2(*(__half2*)&v0.x); a0.x += f.x; a0.y += f.y;
            f = __half22float2(*(__half2*)&v0.y); a0.z += f.x; a0.w += f.y;
            f = __half22float2(*(__half2*)&v1.x); a1.x += f.x; a1.y += f.y;
            f = __half22float2(*(__half2*)&v1.y); a1.z += f.x; a1.w += f.y;
            f = __half22float2(*(__half2*)&v2.x); a0.x += f.x; a0.y += f.y;
            f = __half22float2(*(__half2*)&v2.y); a0.z += f.x; a0.w += f.y;
            f = __half22float2(*(__half2*)&v3.x); a1.x += f.x; a1.y += f.y;
            f = __half22float2(*(__half2*)&v3.y); a1.z += f.x; a1.w += f.y;
        }
        for (; e < e1; e++) {
            int s0 = __ldg(&col[e]);
            uint2 v0 = __ldg(&z2[(size_t)s0 * 32 + lane]);
            float2 f;
            f = __half22float2(*(__half2*)&v0.x); a0.x += f.x; a0.y += f.y;
            f = __half22float2(*(__half2*)&v0.y); a0.z += f.x; a0.w += f.y;
        }
    }

    float s  = (row < N) ? __ldg(&nd[row]) : 0.f;
    float4 bb = __ldg(((const float4*)b) + lane);
    float4 o;
    o.x = fmaxf((a0.x + a1.x) * s + bb.x, 0.f);
    o.y = fmaxf((a0.y + a1.y) * s + bb.y, 0.f);
    o.z = fmaxf((a0.z + a1.z) * s + bb.z, 0.f);
    o.w = fmaxf((a0.w + a1.w) * s + bb.w, 0.f);

    if (!POOL) {
        if (row < N) {
            // words ua (cols o.x,o.y) and ub (cols o.z,o.w), interleaved layout:
            // hi at (u>>1)*4 + (u&1), lo at (u>>1)*4 + 2 + (u&1)
            unsigned* xp = (unsigned*)X4 + (size_t)row * 128;
            int ua = chunk_u(2 * lane);
            int ub = chunk_u(2 * lane + 1);
            unsigned hp, lp;
            split2h(o.x, o.y, hp, lp);
            xp[(ua >> 1) * 4 + (ua & 1)]     = hp;
            xp[(ua >> 1) * 4 + 2 + (ua & 1)] = lp;
            split2h(o.z, o.w, hp, lp);
            xp[(ub >> 1) * 4 + (ub & 1)]     = hp;
            xp[(ub >> 1) * 4 + 2 + (ub & 1)] = lp;
        }
    } else {
        __shared__ float4 so[8][32];
        __shared__ int    sg[8];
        so[wid][lane] = o;
        if (lane == 0) sg[wid] = (row < N) ? __ldg(&gid_arr[row]) : -1;
        __syncthreads();
        if (wid == 0) {
            int cur = -1;
            float4 s4 = make_float4(0.f, 0.f, 0.f, 0.f);
#pragma unroll
            for (int r = 0; r < 8; r++) {
                int g = sg[r];
                if (g < 0) break;
                float4 v = so[r][lane];
                if (g != cur) {
                    if (cur >= 0) redv4(gsum + (size_t)cur * D + lane * 4, s4);
                    cur = g;
                    s4 = v;
                } else {
                    s4.x += v.x; s4.y += v.y; s4.z += v.z; s4.w += v.w;
                }
            }
            if (cur >= 0) redv4(gsum + (size_t)cur * D + lane * 4, s4);
        }
    }
}

// ---------------- final: mean = gsum / count (binary search) -----------------
__global__ void k_final(const float* __restrict__ gsum, const int* __restrict__ gid,
                        float* __restrict__ out, int N) {
    int i = blockIdx.x * blockDim.x + threadIdx.x;
    if (i >= GMAX * D) return;
    int g = i >> 7;
    int lo = 0, hi = N;
    while (lo < hi) { int m = (lo + hi) >> 1; if (gid[m] < g) lo = m + 1; else hi = m; }
    int lb = lo;
    lo = 0; hi = N;
    while (lo < hi) { int m = (lo + hi) >> 1; if (gid[m] <= g) lo = m + 1; else hi = m; }
    float c = (float)(lo - lb);
    out[i] = gsum[i] / fmaxf(c, 1.0f);
}

// ---------------- trailing re-init for next replay ---------------------------
__global__ void k_reinit(float* __restrict__ ns, float* __restrict__ nd,
                         float* __restrict__ gsum, int N) {
    int i = blockIdx.x * blockDim.x + threadIdx.x;
    int stride = gridDim.x * blockDim.x;
    for (int j = i; j < N; j += stride) { ns[j] = 0.0f; nd[j] = 0.0f; }
    for (int j = i; j < GMAX * D; j += stride) gsum[j] = 0.0f;
}

// ---------------- launch ------------------------------------------------------
extern "C" void kernel_launch(void* const* d_in, const int* in_sizes, int n_in,
                              void* d_out, int out_size) {
    const float* h   = (const float*)d_in[0];
    const int*   src = (const int*)d_in[1];
    const int*   dst = (const int*)d_in[2];
    const int*   gid = (const int*)d_in[3];
    const float* W1 = (const float*)d_in[4];
    const float* b1 = (const float*)d_in[5];
    const float* W2 = (const float*)d_in[6];
    const float* b2 = (const float*)d_in[7];
    const float* W3 = (const float*)d_in[8];
    const float* b3 = (const float*)d_in[9];

    int N = in_sizes[0] / D;
    int E = in_sizes[1];
    float* out = (float*)d_out;

    uint4 *x4;
    uint2 *w2;
    __half *zh;
    float *ns, *nd, *gsum;
    int *row_start, *cursor, *col;
    cudaGetSymbolAddress((void**)&x4,   g_x4);
    cudaGetSymbolAddress((void**)&w2,   g_w2);
    cudaGetSymbolAddress((void**)&zh,   g_zh);
    cudaGetSymbolAddress((void**)&ns,   g_ns);
    cudaGetSymbolAddress((void**)&nd,   g_nd);
    cudaGetSymbolAddress((void**)&gsum, g_gsum);
    cudaGetSymbolAddress((void**)&row_start, g_row_start);
    cudaGetSymbolAddress((void**)&cursor,    g_cursor);
    cudaGetSymbolAddress((void**)&col,       g_col);

    int gemmBlocks   = (N + 127) / 128;
    int gatherBlocks = (N + 7) / 8;

    // #1: degrees + X/W plane conversion
    k_prep<<<4096, 256>>>(src, dst, ns, nd, E, h, x4, N, W1, W2, W3, w2);
    // #2: row_start + cursor + norms
    k_rowstart_norm<<<(N + 255) / 256, 256>>>(ns, nd, row_start, cursor, N, E);
    // #3: CSR fill
    k_fill<<<(E + 255) / 256, 256>>>(src, dst, cursor, col, E);

    // layer 1 (#4 = gemm -> ncu capture slot)
    k_gemm<<<gemmBlocks, 256>>>(x4, w2, ns, zh, N);
    k_gather<false><<<gatherBlocks, 256>>>(zh, row_start, col, nd, b1, x4,
                                           nullptr, nullptr, N);
    // layer 2
    k_gemm<<<gemmBlocks, 256>>>(x4, w2 + 4096, ns, zh, N);
    k_gather<false><<<gatherBlocks, 256>>>(zh, row_start, col, nd, b2, x4,
                                           nullptr, nullptr, N);
    // layer 3 -> pooled sums
    k_gemm<<<gemmBlocks, 256>>>(x4, w2 + 8192, ns, zh, N);
    k_gather<true><<<gatherBlocks, 256>>>(zh, row_start, col, nd, b3, nullptr,
                                          gid, gsum, N);

    // mean + reinit
    k_final<<<(GMAX * D + 255) / 256, 256>>>(gsum, gid, out, N);
    k_reinit<<<128, 256>>>(ns, nd, gsum, N);
}

// round 17
// speedup vs baseline: 1.1265x; 1.1265x over previous
#include <cuda_runtime.h>
#include <cuda_fp16.h>

#define D     128
#define NMAX  50000
#define EMAX  600000
#define GMAX  64

// ---------------- device scratch ---------------------------------------------
// X planes interleaved (fp16): X4[r*32 + j] = {hi(2j), hi(2j+1), lo(2j), lo(2j+1)}
__device__ uint4 g_x4[NMAX * 32];
// W^T single fp16 plane per layer: W2[l*4096 + n*32 + j] = {w(2j), w(2j+1)}
__device__ uint2 g_w2[3 * 4096];
__device__ __half g_zh[NMAX * D];                // Z = (X @ W) * ns  (fp16)
__device__ float g_ns[NMAX];
__device__ float g_nd[NMAX];
__device__ float g_gsum[GMAX * D];
__device__ int   g_row_start[NMAX + 1];
__device__ int   g_cursor[NMAX];
__device__ int   g_col[EMAX];

// ---------------- helpers ----------------------------------------------------
__device__ __forceinline__ void redv4(float* p, float4 v) {
    asm volatile(
        "{\n\t"
        ".reg .u64 gp;\n\t"
        "cvta.to.global.u64 gp, %0;\n\t"
        "red.global.add.v4.f32 [gp], {%1, %2, %3, %4};\n\t"
        "}"
        :: "l"(p), "f"(v.x), "f"(v.y), "f"(v.z), "f"(v.w)
        : "memory");
}

// m16n8k16 fp16 MMA, fp32 accum (layout per CUTLASS SM80_16x8x16 TN)
__device__ __forceinline__ void mma_fp16(float c[4], const unsigned a[4],
                                         unsigned b0, unsigned b1) {
    asm("mma.sync.aligned.m16n8k16.row.col.f32.f16.f16.f32 "
        "{%0,%1,%2,%3}, {%4,%5,%6,%7}, {%8,%9}, {%0,%1,%2,%3};"
        : "+f"(c[0]), "+f"(c[1]), "+f"(c[2]), "+f"(c[3])
        : "r"(a[0]), "r"(a[1]), "r"(a[2]), "r"(a[3]), "r"(b0), "r"(b1));
}

// word index u (0..63) for fp16-pair k2 (0..63): u = ks*8 + tig*2 + kh
__device__ __forceinline__ int chunk_u(int k2) {
    return ((k2 >> 3) << 3) + ((k2 & 3) << 1) + ((k2 >> 2) & 1);
}

// pack two f32 -> fp16x2
__device__ __forceinline__ unsigned h2pack(float e0, float e1) {
    __half2 h = __floats2half2_rn(e0, e1);
    return *(unsigned*)&h;
}

// split one f32 pair into fp16 hi/lo planes (hi + lo represents x to ~2^-23)
__device__ __forceinline__ void split2h(float x0, float x1, unsigned& hp, unsigned& lp) {
    __half2 h = __floats2half2_rn(x0, x1);
    float2 r = __half22float2(h);
    __half2 l = __floats2half2_rn(x0 - r.x, x1 - r.y);
    hp = *(unsigned*)&h;
    lp = *(unsigned*)&l;
}

// ---------------- #1: degrees + X-plane convert + W-plane convert ------------
__global__ __launch_bounds__(256)
void k_prep(const int* __restrict__ src, const int* __restrict__ dst,
            float* __restrict__ ns, float* __restrict__ nd, int E,
            const float* __restrict__ h, uint4* __restrict__ X4, int N,
            const float* __restrict__ W1, const float* __restrict__ W2,
            const float* __restrict__ W3, uint2* __restrict__ Wp) {
    int g = blockIdx.x * blockDim.x + threadIdx.x;
    int stride = gridDim.x * blockDim.x;

    for (int e = g; e < E; e += stride) {
        atomicAdd(&ns[src[e]], 1.0f);
        atomicAdd(&nd[dst[e]], 1.0f);
    }

    // X: one uint4 per (r, j); words 2j (k2a) and 2j+1 (k2b), fp16 hi/lo
    int nx = N * 32;
    for (int i = g; i < nx; i += stride) {
        int r = i >> 5, j = i & 31;
        int ks = j >> 2, tig = j & 3;
        int k2a = ks * 8 + tig;        // kh = 0
        int k2b = ks * 8 + 4 + tig;    // kh = 1
        float2 va = *(const float2*)(h + (size_t)r * 128 + k2a * 2);
        float2 vb = *(const float2*)(h + (size_t)r * 128 + k2b * 2);
        unsigned h0, l0, h1, l1;
        split2h(va.x, va.y, h0, l0);
        split2h(vb.x, vb.y, h1, l1);
        X4[i] = make_uint4(h0, h1, l0, l1);
    }

    // W^T: one uint2 per (l, n, j); single fp16 plane; source W[k][n]
    for (int i = g; i < 3 * 4096; i += stride) {
        int l = i >> 12, j2 = i & 4095;
        int n = j2 >> 5, j = j2 & 31;
        int ks = j >> 2, tig = j & 3;
        int k2a = ks * 8 + tig;
        int k2b = ks * 8 + 4 + tig;
        const float* W = (l == 0) ? W1 : (l == 1) ? W2 : W3;
        unsigned w0 = h2pack(W[(2 * k2a) * 128 + n], W[(2 * k2a + 1) * 128 + n]);
        unsigned w1 = h2pack(W[(2 * k2b) * 128 + n], W[(2 * k2b + 1) * 128 + n]);
        Wp[i] = make_uint2(w0, w1);
    }
}

// ---------------- #2: row_start scan + cursor + norms ------------------------
__global__ __launch_bounds__(256)
void k_rowstart_norm(float* __restrict__ ns, float* __restrict__ nd,
                     int* __restrict__ row_start, int* __restrict__ cursor,
                     int N, int E) {
    __shared__ int s[256];
    int tid = threadIdx.x;
    int base0 = blockIdx.x * 256;

    int acc = 0;
    for (int i = tid; i < base0; i += 256) acc += (int)nd[i];
    s[tid] = acc;
    __syncthreads();
    for (int off = 128; off > 0; off >>= 1) {
        if (tid < off) s[tid] += s[tid + off];
        __syncthreads();
    }
    int base = s[0];
    __syncthreads();

    int i = base0 + tid;
    int deg = (i < N) ? (int)nd[i] : 0;
    s[tid] = deg;
    __syncthreads();
    for (int off = 1; off < 256; off <<= 1) {
        int t = (tid >= off) ? s[tid - off] : 0;
        __syncthreads();
        s[tid] += t;
        __syncthreads();
    }

    if (i < N) {
        int rs = base + s[tid] - deg;
        row_start[i] = rs;
        cursor[i] = rs;
        if (i == N - 1) row_start[N] = E;
        ns[i] = rsqrtf(fmaxf(ns[i], 1.0f));
        nd[i] = rsqrtf(fmaxf(nd[i], 1.0f));
    }
}

// ---------------- #3: scatter edges into CSR ---------------------------------
__global__ void k_fill(const int* __restrict__ src, const int* __restrict__ dst,
                       int* __restrict__ cursor, int* __restrict__ col, int E) {
    int e = blockIdx.x * blockDim.x + threadIdx.x;
    if (e < E) {
        int pos = atomicAdd(&cursor[dst[e]], 1);
        col[pos] = src[e];
    }
}

// ---------------- tensor-core GEMM: Z = (X @ W) * ns[:,None] -----------------
// 2-product fp16 split ((Xh + Xl) @ W_fp16), fp32 accum. EXACT R15 warp body;
// block widened to 384 threads (12 warps, 192x128 tile, 3 row-bands x 4
// col-bands): 3 warps/SMSP instead of 2 with only a 4-reg cap (170 vs 174).
__global__ __launch_bounds__(384)
void k_gemm(const uint4* __restrict__ X4, const uint2* __restrict__ Wp,
            const float* __restrict__ ns, __half* __restrict__ Zh, int N) {
    int tid  = threadIdx.x;
    int lane = tid & 31;
    int wid  = tid >> 5;       // 0..11
    int gid  = lane >> 2;      // 0..7
    int tig  = lane & 3;       // 0..3

    int wm = wid % 3;          // row band 0..2
    int wn = wid / 3;          // col band 0..3
    int row0  = blockIdx.x * 192 + wm * 64;
    int nbase = wn * 32;

    float c[4][4][4];
#pragma unroll
    for (int mt = 0; mt < 4; mt++)
#pragma unroll
        for (int nt = 0; nt < 4; nt++)
#pragma unroll
            for (int q = 0; q < 4; q++) c[mt][nt][q] = 0.f;

#pragma unroll
    for (int ks = 0; ks < 8; ks++) {
        unsigned ah[4][4], al[4][4];
#pragma unroll
        for (int mt = 0; mt < 4; mt++) {
            int r  = row0 + mt * 16 + gid;
            int r8 = r + 8;
            int rc  = (r  < N) ? r  : N - 1;
            int rc8 = (r8 < N) ? r8 : N - 1;
            uint4 v1 = __ldg(&X4[(size_t)rc  * 32 + ks * 4 + tig]); // a0,a2 planes
            uint4 v2 = __ldg(&X4[(size_t)rc8 * 32 + ks * 4 + tig]); // a1,a3 planes
            ah[mt][0] = v1.x; ah[mt][2] = v1.y;
            ah[mt][1] = v2.x; ah[mt][3] = v2.y;
            al[mt][0] = v1.z; al[mt][2] = v1.w;
            al[mt][1] = v2.z; al[mt][3] = v2.w;
        }
#pragma unroll
        for (int nt = 0; nt < 4; nt++) {
            int n = nbase + nt * 8 + gid;
            uint2 B = __ldg(&Wp[n * 32 + ks * 4 + tig]);  // {b0, b1} fp16 plane
#pragma unroll
            for (int mt = 0; mt < 4; mt++) {
                mma_fp16(c[mt][nt], ah[mt], B.x, B.y);
                mma_fp16(c[mt][nt], al[mt], B.x, B.y);
            }
        }
    }

#pragma unroll
    for (int mt = 0; mt < 4; mt++) {
        int r  = row0 + mt * 16 + gid;
        int r8 = r + 8;
        float s1 = (r  < N) ? __ldg(&ns[r])  : 0.f;
        float s2 = (r8 < N) ? __ldg(&ns[r8]) : 0.f;
#pragma unroll
        for (int nt = 0; nt < 4; nt++) {
            int colx = nbase + nt * 8 + tig * 2;
            if (r < N)
                *(__half2*)(Zh + (size_t)r * 128 + colx) =
                    __floats2half2_rn(c[mt][nt][0] * s1, c[mt][nt][1] * s1);
            if (r8 < N)
                *(__half2*)(Zh + (size_t)r8 * 128 + colx) =
                    __floats2half2_rn(c[mt][nt][2] * s2, c[mt][nt][3] * s2);
        }
    }
}

// ---------------- gather: y = relu(nd * segsum(Z[src]) + b) ------------------
// Warp per destination row; Z is fp16 (half the LTS bytes), fp32 accumulate.
// POOL=false: writes interleaved fp16 hi/lo planes for the next layer.
// POOL=true: per-graph smem merge + vector REDs into gsum.
template <bool POOL>
__global__ __launch_bounds__(256)
void k_gather(const __half* __restrict__ Zh,
              const int* __restrict__ row_start, const int* __restrict__ col,
              const float* __restrict__ nd, const float* __restrict__ b,
              uint4* __restrict__ X4,
              const int* __restrict__ gid_arr, float* __restrict__ gsum, int N) {
    int tid  = threadIdx.x;
    int lane = tid & 31;
    int wid  = tid >> 5;
    int row  = blockIdx.x * 8 + wid;

    const uint2* z2 = (const uint2*)Zh;   // 4 halves per lane (cols lane*4..+3)
    float4 a0 = make_float4(0.f, 0.f, 0.f, 0.f);
    float4 a1 = make_float4(0.f, 0.f, 0.f, 0.f);

    if (row < N) {
        int e0 = __ldg(&row_start[row]);
        int e1 = __ldg(&row_start[row + 1]);
        int e  = e0;
        for (; e + 3 < e1; e += 4) {
            int s0 = __ldg(&col[e]);
            int s1 = __ldg(&col[e + 1]);
            int s2 = __ldg(&col[e + 2]);
            int s3 = __ldg(&col[e + 3]);
            uint2 v0 = __ldg(&z2[(size_t)s0 * 32 + lane]);
            uint2 v1 = __ldg(&z2[(size_t)s1 * 32 + lane]);
            uint2 v2 = __ldg(&z2[(size_t)s2 * 32 + lane]);
            uint2 v3 = __ldg(&z2[(size_t)s3 * 32 + lane]);
            float2 f;
            f = __half22float2(*(__half2*)&v0.x); a0.x += f.x; a0.y += f.y;
            f = __half22float2(*(__half2*)&v0.y); a0.z += f.x; a0.w += f.y;
            f = __half22float2(*(__half2*)&v1.x); a1.x += f.x; a1.y += f.y;
            f = __half22float2(*(__half2*)&v1.y); a1.z += f.x; a1.w += f.y;
            f = __half22float2(*(__half2*)&v2.x); a0.x += f.x; a0.y += f.y;
            f = __half22float2(*(__half2*)&v2.y); a0.z += f.x; a0.w += f.y;
            f = __half22float2(*(__half2*)&v3.x); a1.x += f.x; a1.y += f.y;
            f = __half22float2(*(__half2*)&v3.y); a1.z += f.x; a1.w += f.y;
        }
        for (; e < e1; e++) {
            int s0 = __ldg(&col[e]);
            uint2 v0 = __ldg(&z2[(size_t)s0 * 32 + lane]);
            float2 f;
            f = __half22float2(*(__half2*)&v0.x); a0.x += f.x; a0.y += f.y;
            f = __half22float2(*(__half2*)&v0.y); a0.z += f.x; a0.w += f.y;
        }
    }

    float s  = (row < N) ? __ldg(&nd[row]) : 0.f;
    float4 bb = __ldg(((const float4*)b) + lane);
    float4 o;
    o.x = fmaxf((a0.x + a1.x) * s + bb.x, 0.f);
    o.y = fmaxf((a0.y + a1.y) * s + bb.y, 0.f);
    o.z = fmaxf((a0.z + a1.z) * s + bb.z, 0.f);
    o.w = fmaxf((a0.w + a1.w) * s + bb.w, 0.f);

    if (!POOL) {
        if (row < N) {
            // words ua (cols o.x,o.y) and ub (cols o.z,o.w), interleaved layout:
            // hi at (u>>1)*4 + (u&1), lo at (u>>1)*4 + 2 + (u&1)
            unsigned* xp = (unsigned*)X4 + (size_t)row * 128;
            int ua = chunk_u(2 * lane);
            int ub = chunk_u(2 * lane + 1);
            unsigned hp, lp;
            split2h(o.x, o.y, hp, lp);
            xp[(ua >> 1) * 4 + (ua & 1)]     = hp;
            xp[(ua >> 1) * 4 + 2 + (ua & 1)] = lp;
            split2h(o.z, o.w, hp, lp);
            xp[(ub >> 1) * 4 + (ub & 1)]     = hp;
            xp[(ub >> 1) * 4 + 2 + (ub & 1)] = lp;
        }
    } else {
        __shared__ float4 so[8][32];
        __shared__ int    sg[8];
        so[wid][lane] = o;
        if (lane == 0) sg[wid] = (row < N) ? __ldg(&gid_arr[row]) : -1;
        __syncthreads();
        if (wid == 0) {
            int cur = -1;
            float4 s4 = make_float4(0.f, 0.f, 0.f, 0.f);
#pragma unroll
            for (int r = 0; r < 8; r++) {
                int g = sg[r];
                if (g < 0) break;
                float4 v = so[r][lane];
                if (g != cur) {
                    if (cur >= 0) redv4(gsum + (size_t)cur * D + lane * 4, s4);
                    cur = g;
                    s4 = v;
                } else {
                    s4.x += v.x; s4.y += v.y; s4.z += v.z; s4.w += v.w;
                }
            }
            if (cur >= 0) redv4(gsum + (size_t)cur * D + lane * 4, s4);
        }
    }
}

// ---------------- final: mean = gsum / count (binary search) -----------------
__global__ void k_final(const float* __restrict__ gsum, const int* __restrict__ gid,
                        float* __restrict__ out, int N) {
    int i = blockIdx.x * blockDim.x + threadIdx.x;
    if (i >= GMAX * D) return;
    int g = i >> 7;
    int lo = 0, hi = N;
    while (lo < hi) { int m = (lo + hi) >> 1; if (gid[m] < g) lo = m + 1; else hi = m; }
    int lb = lo;
    lo = 0; hi = N;
    while (lo < hi) { int m = (lo + hi) >> 1; if (gid[m] <= g) lo = m + 1; else hi = m; }
    float c = (float)(lo - lb);
    out[i] = gsum[i] / fmaxf(c, 1.0f);
}

// ---------------- trailing re-init for next replay ---------------------------
__global__ void k_reinit(float* __restrict__ ns, float* __restrict__ nd,
                         float* __restrict__ gsum, int N) {
    int i = blockIdx.x * blockDim.x + threadIdx.x;
    int stride = gridDim.x * blockDim.x;
    for (int j = i; j < N; j += stride) { ns[j] = 0.0f; nd[j] = 0.0f; }
    for (int j = i; j < GMAX * D; j += stride) gsum[j] = 0.0f;
}

// ---------------- launch ------------------------------------------------------
extern "C" void kernel_launch(void* const* d_in, const int* in_sizes, int n_in,
                              void* d_out, int out_size) {
    const float* h   = (const float*)d_in[0];
    const int*   src = (const int*)d_in[1];
    const int*   dst = (const int*)d_in[2];
    const int*   gid = (const int*)d_in[3];
    const float* W1 = (const float*)d_in[4];
    const float* b1 = (const float*)d_in[5];
    const float* W2 = (const float*)d_in[6];
    const float* b2 = (const float*)d_in[7];
    const float* W3 = (const float*)d_in[8];
    const float* b3 = (const float*)d_in[9];

    int N = in_sizes[0] / D;
    int E = in_sizes[1];
    float* out = (float*)d_out;

    uint4 *x4;
    uint2 *w2;
    __half *zh;
    float *ns, *nd, *gsum;
    int *row_start, *cursor, *col;
    cudaGetSymbolAddress((void**)&x4,   g_x4);
    cudaGetSymbolAddress((void**)&w2,   g_w2);
    cudaGetSymbolAddress((void**)&zh,   g_zh);
    cudaGetSymbolAddress((void**)&ns,   g_ns);
    cudaGetSymbolAddress((void**)&nd,   g_nd);
    cudaGetSymbolAddress((void**)&gsum, g_gsum);
    cudaGetSymbolAddress((void**)&row_start, g_row_start);
    cudaGetSymbolAddress((void**)&cursor,    g_cursor);
    cudaGetSymbolAddress((void**)&col,       g_col);

    int gemmBlocks   = (N + 191) / 192;
    int gatherBlocks = (N + 7) / 8;

    // #1: degrees + X/W plane conversion
    k_prep<<<4096, 256>>>(src, dst, ns, nd, E, h, x4, N, W1, W2, W3, w2);
    // #2: row_start + cursor + norms
    k_rowstart_norm<<<(N + 255) / 256, 256>>>(ns, nd, row_start, cursor, N, E);
    // #3: CSR fill
    k_fill<<<(E + 255) / 256, 256>>>(src, dst, cursor, col, E);

    // layer 1 (#4 = gemm -> ncu capture slot)
    k_gemm<<<gemmBlocks, 384>>>(x4, w2, ns, zh, N);
    k_gather<false><<<gatherBlocks, 256>>>(zh, row_start, col, nd, b1, x4,
                                           nullptr, nullptr, N);
    // layer 2
    k_gemm<<<gemmBlocks, 384>>>(x4, w2 + 4096, ns, zh, N);
    k_gather<false><<<gatherBlocks, 256>>>(zh, row_start, col, nd, b2, x4,
                                           nullptr, nullptr, N);
    // layer 3 -> pooled sums
    k_gemm<<<gemmBlocks, 384>>>(x4, w2 + 8192, ns, zh, N);
    k_gather<true><<<gatherBlocks, 256>>>(zh, row_start, col, nd, b3, nullptr,
                                          gid, gsum, N);

    // mean + reinit
    k_final<<<(GMAX * D + 255) / 256, 256>>>(gsum, gid, out, N);
    k_reinit<<<128, 256>>>(ns, nd, gsum, N);
}